// round 13
// baseline (speedup 1.0000x reference)
#include <cuda_runtime.h>

#define IMG_H 1536
#define IMG_W 1536
#define NK 8
#define PW 7
#define NR 28      // CLIP_MAX+1 rows of F ever used
#define CLIPM 27

#define BS1 128                   // threads per phase-1 work unit
#define NCH 4                     // row chunks of 7
#define JB (IMG_W / BS1)          // 12 j-blocks
#define NUNITS (NK * NCH * JB)    // 384 compute units; unit 384 = setup
#define NCLS 225                  // fixed candidate row classes: 1 + 8*28
#define NSPLIT 3
#define MAXSPL 75                 // classes per split (225 = 3*75)
#define TC 32                     // columns per phase-2 tile
#define NROWS (NK * NR)           // 224
#define NBLK 144                  // 48 col-tiles * 3 splits; 1 block/SM, all resident
#define TPB 384

// Scratch (device globals only — no allocation allowed). Zero-initialized at
// load; the last block of every launch resets the atomics for graph replay.
__device__ __align__(16) float g_F[NROWS * IMG_W];
__device__ __align__(16) int2  g_tap[NSPLIT * MAXSPL * 32]; // (.x=row, .y=weight bits)
__device__ int      g_tapn[NSPLIT * MAXSPL];
__device__ unsigned g_enc, g_bar1, g_bar2;

// Monotone float <-> uint encoding for atomicMax over signed floats.
__device__ __forceinline__ unsigned enc_f(float f) {
    int b = __float_as_int(f);
    return (b >= 0) ? ((unsigned)b | 0x80000000u) : ~(unsigned)b;
}
__device__ __forceinline__ float dec_f(unsigned u) {
    int b = (u & 0x80000000u) ? (int)(u ^ 0x80000000u) : ~(int)u;
    return __int_as_float(b);
}

__global__ void __launch_bounds__(TPB) geneo_fused(
        const float* __restrict__ x,
        const float* __restrict__ patterns,
        const float* __restrict__ vectors,
        float* __restrict__ out) {
    __shared__ __align__(16) float sF[NROWS * TC];      // 28672 B
    __shared__ __align__(16) int2  sT[MAXSPL * 32];     // 19200 B
    __shared__ int   sTn[MAXSPL];                       //   300 B
    __shared__ float smax[12];
    const int tid  = threadIdx.x;
    const int slot = blockIdx.x * 3 + (tid >> 7);       // phase-1 work unit
    const int ltid = tid & 127;

    // ======================= PHASE 1 =======================
    if (slot < NUNITS) {
        // --- geneo1 rolling-window unit (identical numerics to reference:
        //     a-major/b-minor single chain, so F[k,0,0]==thr bitwise) ---
        const int k   = slot / (NCH * JB);
        const int rem = slot % (NCH * JB);
        const int r0  = (rem / JB) * 7;
        const int j   = (rem % JB) * BS1 + ltid;

        float p[PW * PW];
        #pragma unroll
        for (int t = 0; t < PW * PW; t++) p[t] = __ldg(&patterns[k * PW * PW + t]);
        float s = 0.0f;
        #pragma unroll
        for (int t = 0; t < PW * PW; t++) s += fabsf(p[t]);
        const float thr = 1.0f - s * (1.0f / 49.0f);

        float win[PW][PW];
        #pragma unroll
        for (int a = 0; a < PW; a++) {
            const int r = r0 - PW + a;
            #pragma unroll
            for (int b = 0; b < PW; b++) {
                const int c = j - PW + b;
                win[a][b] = (r >= 0 && c >= 0) ? __ldg(&x[r * IMG_W + c]) : 0.0f;
            }
        }
        #pragma unroll
        for (int step = 0; step < PW; step++) {
            const int row = r0 + step;
            float acc = 0.0f;
            #pragma unroll
            for (int a = 0; a < PW; a++)
                #pragma unroll
                for (int b = 0; b < PW; b++)
                    acc += fabsf(p[a * PW + b] - win[a][b]);
            const float f = 1.0f - acc * (1.0f / 49.0f);
            g_F[(k * NR + row) * IMG_W + j] = (f > thr) ? f : 0.0f;
            if (step < PW - 1) {
                #pragma unroll
                for (int a = 0; a < PW - 1; a++)
                    #pragma unroll
                    for (int b = 0; b < PW; b++)
                        win[a][b] = win[a + 1][b];
                #pragma unroll
                for (int b = 0; b < PW; b++) {
                    const int c = j - PW + b;
                    win[PW - 1][b] = (c >= 0) ? __ldg(&x[row * IMG_W + c]) : 0.0f;
                }
            }
        }
    } else if (slot == NUNITS) {
        // --- setup: merged tap tables; one class per warp iteration.
        // Duplicate rows only occur within a k's 4 corners (row id kk*28+r is
        // unique across k), so a quad merge is a COMPLETE merge.
        const int w = ltid >> 5;                        // warp in group 0..3
        const int l = ltid & 31;                        // lane = tap
        const int kk = l >> 2, c = l & 3;
        const int qb = l & ~3, qi = l & 3;              // quad base / index
        const int dx = c >> 1, dy = c & 1;              // corner order = reference

        for (int cls = w; cls < NCLS; cls += 4) {
            int i; bool valid;
            if (cls == 0) { i = 0; valid = true; }
            else {
                const int e = cls - 1;
                const int kq = e / NR, off = e % NR;
                const int sy0 = (int)floorf(__ldg(&vectors[2 * kq + 1]));
                i = sy0 + 1 + off;
                valid = (i >= 1 && i < IMG_H);
            }
            const float v0 = __ldg(&vectors[2 * kk + 0]);
            const float v1 = __ldg(&vectors[2 * kk + 1]);
            const float fx = floorf(v0), fy = floorf(v1);
            const int   sx = (int)fx,   sy = (int)fy;
            const float px = fx - v0,   py = fy - v1;
            const float wt = (dx ? (1.0f - px) : px) * (dy ? (1.0f - py) : py);
            int t1 = i - (sy + dy);
            t1 = min(max(t1, 0), CLIPM);
            int r = t1 - (sx + dx);
            r = min(max(r, 0), CLIPM);
            const int row = kk * NR + r;

            // quad merge (3 partner shuffles each for row & weight)
            int   rr[4]; float ww[4];
            #pragma unroll
            for (int q = 0; q < 4; q++) {
                rr[q] = __shfl_sync(0xffffffffu, row, qb + q);
                ww[q] = __shfl_sync(0xffffffffu, wt,  qb + q);
            }
            bool leader = true;
            float wsum = wt;
            #pragma unroll
            for (int q = 0; q < 4; q++) {
                if (q < qi && rr[q] == row) leader = false;
                if (q > qi && rr[q] == row) wsum += ww[q];
            }
            const unsigned lead = __ballot_sync(0xffffffffu, leader);
            const int pos = __popc(lead & ((1u << l) - 1u));
            const int split = cls % NSPLIT, m = cls / NSPLIT;
            const int idx0  = (split * MAXSPL + m) * 32;
            if (valid && leader)
                g_tap[idx0 + pos] = make_int2(row, __float_as_int(wsum));
            if (l == 0)
                g_tapn[split * MAXSPL + m] = valid ? __popc(lead) : 0;
        }
    }

    // ======================= GRID BARRIER =======================
    __syncthreads();
    if (tid == 0) {
        __threadfence();
        atomicAdd(&g_bar1, 1u);
        while (atomicOr(&g_bar1, 0u) < (unsigned)NBLK) __nanosleep(32);
    }
    __syncthreads();

    // ======================= PHASE 2 =======================
    const int split = blockIdx.x % NSPLIT;
    const int j0    = (blockIdx.x / NSPLIT) * TC;

    // Stage F tile (ld.cg: fresh from L2 past the fence).
    for (int e = tid; e < NROWS * (TC / 4); e += TPB) {
        const int row = e >> 3;
        const int q   = e & 7;
        ((float4*)sF)[row * (TC / 4) + q] =
            __ldcg((const float4*)&g_F[row * IMG_W + j0 + q * 4]);
    }
    // Stage this split's tap slice + counts.
    {
        const int4* src = (const int4*)&g_tap[split * MAXSPL * 32];
        for (int e = tid; e < MAXSPL * 32 / 2; e += TPB)
            ((int4*)sT)[e] = __ldcg(&src[e]);
        if (tid < MAXSPL) sTn[tid] = __ldcg(&g_tapn[split * MAXSPL + tid]);
    }
    __syncthreads();

    const int lane8 = tid & 7;                  // col-quad within class
    const int cgrp  = tid >> 3;                 // 0..47
    float m = -3.0e38f;

    #pragma unroll
    for (int it = 0; it < 2; it++) {
        const int midx = cgrp + 48 * it;
        if (midx < MAXSPL) {
            const int nt = sTn[midx];
            float4 acc = make_float4(0.f, 0.f, 0.f, 0.f);
            #pragma unroll 8
            for (int t = 0; t < nt; t++) {
                const int2  mt = sT[midx * 32 + t];
                const float wv = __int_as_float(mt.y);
                const float4 v = ((const float4*)sF)[mt.x * (TC / 4) + lane8];
                acc.x = fmaf(wv, v.x, acc.x);
                acc.y = fmaf(wv, v.y, acc.y);
                acc.z = fmaf(wv, v.z, acc.z);
                acc.w = fmaf(wv, v.w, acc.w);
            }
            if (nt > 0)
                m = fmaxf(m, fmaxf(fmaxf(acc.x, acc.y), fmaxf(acc.z, acc.w)));
        }
    }

    #pragma unroll
    for (int o = 16; o > 0; o >>= 1)
        m = fmaxf(m, __shfl_xor_sync(0xffffffffu, m, o));
    if ((tid & 31) == 0) smax[tid >> 5] = m;
    __syncthreads();
    if (tid == 0) {
        #pragma unroll
        for (int w = 1; w < 12; w++) m = fmaxf(m, smax[w]);
        atomicMax(&g_enc, enc_f(m));
        __threadfence();
        const unsigned old = atomicAdd(&g_bar2, 1u);
        if (old == (unsigned)(NBLK - 1)) {
            out[0] = dec_f(atomicOr(&g_enc, 0u)) * (1.0f / 7.0f);
            // reset for next graph replay (kernel is last writer this launch)
            atomicExch(&g_enc, 0u);
            atomicExch(&g_bar1, 0u);
            atomicExch(&g_bar2, 0u);
        }
    }
}

extern "C" void kernel_launch(void* const* d_in, const int* in_sizes, int n_in,
                              void* d_out, int out_size) {
    const float* x        = (const float*)d_in[0];
    const float* patterns = (const float*)d_in[1];
    const float* vectors  = (const float*)d_in[2];
    float* out = (float*)d_out;

    geneo_fused<<<NBLK, TPB>>>(x, patterns, vectors, out);
}

// round 14
// speedup vs baseline: 1.4113x; 1.4113x over previous
#include <cuda_runtime.h>

#define IMG_H 1536
#define IMG_W 1536
#define NK 8
#define PW 7
#define NR 28      // CLIP_MAX+1 rows of F ever used
#define CLIPM 27

#define BS1 128
#define NCH 4                     // row chunks of 7
#define JB (IMG_W / BS1)          // 12 j-blocks
#define NBLK1 (NK * NCH * JB)     // 384 compute blocks; block NBLK1 = setup
#define NCLS 225                  // max distinct row classes: 1 + 8*28

#define TC 32                     // columns per geneo3 block tile
#define NSPLIT 3                  // class splits (cls mod 3)
#define MAXSPL 75                 // classes per split (225 = 3*75)
#define NBLK3 ((IMG_W / TC) * NSPLIT)   // 144 blocks, ~one per SM
#define NROWS (NK * NR)           // 224

// Scratch (device globals only — no allocation allowed)
__device__ __align__(16) float g_F[NROWS * IMG_W];
// Split-major tap table: g_tap[(split*MAXSPL + m)*32 + t], class = split + 3*m
__device__ __align__(16) int2 g_tap[NSPLIT * MAXSPL * 32];
__device__ int      g_icount;
__device__ unsigned g_enc;             // encoded running max
__device__ unsigned g_done;            // completed geneo3 blocks

// Monotone float <-> uint encoding for atomicMax over signed floats.
__device__ __forceinline__ unsigned enc_f(float f) {
    int b = __float_as_int(f);
    return (b >= 0) ? ((unsigned)b | 0x80000000u) : ~(unsigned)b;
}
__device__ __forceinline__ float dec_f(unsigned u) {
    int b = (u & 0x80000000u) ? (int)(u ^ 0x80000000u) : ~(int)u;
    return __int_as_float(b);
}

// ---------------------------------------------------------------------------
// Kernel A (identical to R12 best): rolling-window geneo1 + setup block.
// Summation order EXACTLY matches the reference so F[k,0,0]==thr bitwise.
// ---------------------------------------------------------------------------
__global__ void __launch_bounds__(BS1) geneo1_kernel(
        const float* __restrict__ x,
        const float* __restrict__ patterns,
        const float* __restrict__ vectors) {
    const int tid = threadIdx.x;

    if (blockIdx.x == NBLK1) {
        __shared__ unsigned char flags[IMG_W];
        __shared__ int s_ilist[NCLS];
        __shared__ int s_cnt;
        for (int i = tid; i < IMG_W; i += BS1) flags[i] = 0;
        __syncthreads();
        if (tid == 0) { flags[0] = 1; g_enc = 0u; g_done = 0u; }
        if (tid < NK * NR) {
            const int k = tid / NR, off = tid % NR;
            const int sy = (int)floorf(vectors[2 * k + 1]);
            const int i = sy + 1 + off;
            if (i >= 1 && i < IMG_W) flags[i] = 1;
        }
        __syncthreads();
        if (tid < 32) {
            int base = 0;
            for (int ch = 0; ch < IMG_W / 32; ch++) {
                const int f = flags[ch * 32 + tid];
                const unsigned m = __ballot_sync(0xffffffffu, f);
                if (f) s_ilist[base + __popc(m & ((1u << tid) - 1u))] = ch * 32 + tid;
                base += __popc(m);
            }
            if (tid == 0) { s_cnt = base; g_icount = base; }
        }
        __syncthreads();

        const int cnt = s_cnt;
        for (int e = tid; e < cnt * 32; e += BS1) {
            const int cls = e >> 5;
            const int t   = e & 31;
            const int i   = s_ilist[cls];
            const int kk  = t >> 2;
            const int c   = t & 3;
            const float v0 = __ldg(&vectors[2 * kk + 0]);
            const float v1 = __ldg(&vectors[2 * kk + 1]);
            const float fx = floorf(v0);
            const float fy = floorf(v1);
            const int   sx = (int)fx;
            const int   sy = (int)fy;
            const float px = fx - v0;
            const float py = fy - v1;
            const int dx = c >> 1;          // corner order matches reference
            const int dy = c & 1;
            const float w = (dx ? (1.0f - px) : px) * (dy ? (1.0f - py) : py);
            int t1 = i - (sy + dy);
            t1 = min(max(t1, 0), CLIPM);
            int r = t1 - (sx + dx);
            r = min(max(r, 0), CLIPM);
            const int split = cls % NSPLIT;
            const int m     = cls / NSPLIT;
            g_tap[(split * MAXSPL + m) * 32 + t] =
                make_int2(kk * NR + r, __float_as_int(w));
        }
        return;
    }

    const int k   = blockIdx.x / (NCH * JB);
    const int rem = blockIdx.x % (NCH * JB);
    const int r0  = (rem / JB) * 7;
    const int j   = (rem % JB) * BS1 + tid;

    float p[PW * PW];
    #pragma unroll
    for (int t = 0; t < PW * PW; t++) p[t] = __ldg(&patterns[k * PW * PW + t]);
    float s = 0.0f;
    #pragma unroll
    for (int t = 0; t < PW * PW; t++) s += fabsf(p[t]);
    const float thr = 1.0f - s * (1.0f / 49.0f);

    float win[PW][PW];
    #pragma unroll
    for (int a = 0; a < PW; a++) {
        const int r = r0 - PW + a;
        #pragma unroll
        for (int b = 0; b < PW; b++) {
            const int c = j - PW + b;
            win[a][b] = (r >= 0 && c >= 0) ? __ldg(&x[r * IMG_W + c]) : 0.0f;
        }
    }

    #pragma unroll
    for (int step = 0; step < PW; step++) {
        const int row = r0 + step;
        float acc = 0.0f;
        #pragma unroll
        for (int a = 0; a < PW; a++)
            #pragma unroll
            for (int b = 0; b < PW; b++)
                acc += fabsf(p[a * PW + b] - win[a][b]);
        const float f = 1.0f - acc * (1.0f / 49.0f);
        g_F[(k * NR + row) * IMG_W + j] = (f > thr) ? f : 0.0f;

        if (step < PW - 1) {
            #pragma unroll
            for (int a = 0; a < PW - 1; a++)
                #pragma unroll
                for (int b = 0; b < PW; b++)
                    win[a][b] = win[a + 1][b];
            #pragma unroll
            for (int b = 0; b < PW; b++) {
                const int c = j - PW + b;
                win[PW - 1][b] = (c >= 0) ? __ldg(&x[row * IMG_W + c]) : 0.0f;
            }
        }
    }
}

// ---------------------------------------------------------------------------
// Kernel B: 144 blocks (48 col-tiles x 3 splits). F tile + tap slice staged
// in smem. Each thread evaluates TWO classes with independent accumulators,
// taps in register-batched groups of 4 (meta loads hoisted before data
// loads) -> ~16 LDS in flight per thread. launch_bounds(384,1) frees the
// register budget so ptxas can actually pipeline the batches.
// ---------------------------------------------------------------------------
__global__ void __launch_bounds__(384, 1) geneo3_kernel(float* __restrict__ out) {
    __shared__ __align__(16) float sF[NROWS * TC];         // 28672 B
    __shared__ __align__(16) int2  sT[MAXSPL * 32];        // 19200 B
    __shared__ float smax[12];
    __shared__ int   scount;
    const int tid   = threadIdx.x;
    const int split = blockIdx.x % NSPLIT;
    const int j0    = (blockIdx.x / NSPLIT) * TC;

    // Stage F tile: 224 rows x 32 cols = 1792 float4.
    for (int e = tid; e < NROWS * (TC / 4); e += 384) {
        const int row = e >> 3;
        const int q   = e & 7;
        ((float4*)sF)[e] = *(const float4*)&g_F[row * IMG_W + j0 + q * 4];
    }
    // Stage tap slice: contiguous 1200 int4.
    {
        const int4* src = (const int4*)&g_tap[split * MAXSPL * 32];
        for (int e = tid; e < MAXSPL * 16; e += 384)
            ((int4*)sT)[e] = __ldg(&src[e]);
    }
    if (tid == 0) scount = g_icount;
    __syncthreads();

    const int count = scount;
    const int lane8 = tid & 7;                 // col-quad within class
    const int cgrp  = tid >> 3;                // 0..47
    const int m0    = cgrp;                    // class index within split
    const int m1    = cgrp + 48;
    const bool valid0 = (split + NSPLIT * m0) < count;
    const bool valid1 = (m1 < MAXSPL) && ((split + NSPLIT * m1) < count);
    const int  t1base = (valid1 ? m1 : m0) * 32;   // alias to stay in bounds

    float4 a0 = make_float4(0.f, 0.f, 0.f, 0.f);
    float4 a1 = make_float4(0.f, 0.f, 0.f, 0.f);

    #pragma unroll
    for (int b = 0; b < 8; b++) {
        // hoist 8 meta loads (independent LDS.64s)
        int2 q0[4], q1[4];
        #pragma unroll
        for (int u = 0; u < 4; u++) {
            q0[u] = sT[m0 * 32 + b * 4 + u];
            q1[u] = sT[t1base  + b * 4 + u];
        }
        // 8 independent LDS.128 + FMAs
        #pragma unroll
        for (int u = 0; u < 4; u++) {
            const float w0 = __int_as_float(q0[u].y);
            const float4 v0 = ((const float4*)sF)[q0[u].x * (TC / 4) + lane8];
            a0.x = fmaf(w0, v0.x, a0.x);
            a0.y = fmaf(w0, v0.y, a0.y);
            a0.z = fmaf(w0, v0.z, a0.z);
            a0.w = fmaf(w0, v0.w, a0.w);
            const float w1 = __int_as_float(q1[u].y);
            const float4 v1 = ((const float4*)sF)[q1[u].x * (TC / 4) + lane8];
            a1.x = fmaf(w1, v1.x, a1.x);
            a1.y = fmaf(w1, v1.y, a1.y);
            a1.z = fmaf(w1, v1.z, a1.z);
            a1.w = fmaf(w1, v1.w, a1.w);
        }
    }

    float m = -3.0e38f;
    if (valid0) m = fmaxf(m, fmaxf(fmaxf(a0.x, a0.y), fmaxf(a0.z, a0.w)));
    if (valid1) m = fmaxf(m, fmaxf(fmaxf(a1.x, a1.y), fmaxf(a1.z, a1.w)));

    #pragma unroll
    for (int o = 16; o > 0; o >>= 1)
        m = fmaxf(m, __shfl_xor_sync(0xffffffffu, m, o));
    if ((tid & 31) == 0) smax[tid >> 5] = m;
    __syncthreads();
    if (tid == 0) {
        #pragma unroll
        for (int w = 1; w < 12; w++) m = fmaxf(m, smax[w]);
        atomicMax(&g_enc, enc_f(m));
        __threadfence();
        const unsigned old = atomicAdd(&g_done, 1u);
        if (old == (unsigned)(NBLK3 - 1)) {
            const unsigned u = atomicOr(&g_enc, 0u);   // coherent read
            out[0] = dec_f(u) * (1.0f / 7.0f);
        }
    }
}

extern "C" void kernel_launch(void* const* d_in, const int* in_sizes, int n_in,
                              void* d_out, int out_size) {
    const float* x        = (const float*)d_in[0];
    const float* patterns = (const float*)d_in[1];
    const float* vectors  = (const float*)d_in[2];
    float* out = (float*)d_out;

    geneo1_kernel<<<NBLK1 + 1, BS1>>>(x, patterns, vectors);
    geneo3_kernel<<<NBLK3, 384>>>(out);
}

// round 16
// speedup vs baseline: 1.6089x; 1.1400x over previous
#include <cuda_runtime.h>

#define IMG_H 1536
#define IMG_W 1536
#define NK 8
#define PW 7
#define NR 28      // CLIP_MAX+1 rows of F ever used
#define CLIPM 27

#define BS1 128
#define NCH 4                     // row chunks of 7
#define JB (IMG_W / BS1)          // 12 j-blocks
#define NBLK1 (NK * NCH * JB)     // 384 compute blocks; block NBLK1 = setup
#define NCLS 225                  // max distinct row classes: 1 + 8*28

#define JT3 12                    // geneo3 column tiles (128 cols each)
#define NBLK3 (NCLS * JT3)        // 2700 blocks x 128 threads

// Scratch (device globals only — no allocation allowed)
__device__ __align__(16) float g_F[NK * NR * IMG_W]; // thresholded F[k][row][j]
__device__ __align__(16) int2  g_tap[NCLS * 32];     // (.x = row*IMG_W, .y = weight bits)
__device__ int      g_icount;
__device__ unsigned g_enc;             // encoded running max
__device__ unsigned g_done;            // completed geneo3 blocks

// Monotone float <-> uint encoding for atomicMax over signed floats.
__device__ __forceinline__ unsigned enc_f(float f) {
    int b = __float_as_int(f);
    return (b >= 0) ? ((unsigned)b | 0x80000000u) : ~(unsigned)b;
}
__device__ __forceinline__ float dec_f(unsigned u) {
    int b = (u & 0x80000000u) ? (int)(u ^ 0x80000000u) : ~(int)u;
    return __int_as_float(b);
}

// ---------------------------------------------------------------------------
// Kernel A: rolling-window geneo1 (exact reference summation order, so
// F[k,0,0]==thr bitwise) + setup block writing the cls-major tap table.
// ---------------------------------------------------------------------------
__global__ void __launch_bounds__(BS1) geneo1_kernel(
        const float* __restrict__ x,
        const float* __restrict__ patterns,
        const float* __restrict__ vectors) {
    const int tid = threadIdx.x;

    if (blockIdx.x == NBLK1) {
        // ---- flag candidate i's, ordered warp-ballot compaction ----
        __shared__ unsigned char flags[IMG_W];
        __shared__ int s_ilist[NCLS];
        __shared__ int s_cnt;
        for (int i = tid; i < IMG_W; i += BS1) flags[i] = 0;
        __syncthreads();
        if (tid == 0) { flags[0] = 1; g_enc = 0u; g_done = 0u; }
        if (tid < NK * NR) {
            const int k = tid / NR, off = tid % NR;
            const int sy = (int)floorf(vectors[2 * k + 1]);
            const int i = sy + 1 + off;
            if (i >= 1 && i < IMG_W) flags[i] = 1;
        }
        __syncthreads();
        if (tid < 32) {
            int base = 0;
            for (int ch = 0; ch < IMG_W / 32; ch++) {
                const int f = flags[ch * 32 + tid];
                const unsigned m = __ballot_sync(0xffffffffu, f);
                if (f) s_ilist[base + __popc(m & ((1u << tid) - 1u))] = ch * 32 + tid;
                base += __popc(m);
            }
            if (tid == 0) { s_cnt = base; g_icount = base; }
        }
        __syncthreads();

        // ---- unmerged cls-major tap table: entries fully independent ----
        const int cnt = s_cnt;
        for (int e = tid; e < cnt * 32; e += BS1) {
            const int cls = e >> 5;
            const int t   = e & 31;
            const int i   = s_ilist[cls];
            const int kk  = t >> 2;
            const int c   = t & 3;
            const float v0 = __ldg(&vectors[2 * kk + 0]);
            const float v1 = __ldg(&vectors[2 * kk + 1]);
            const float fx = floorf(v0);
            const float fy = floorf(v1);
            const int   sx = (int)fx;
            const int   sy = (int)fy;
            const float px = fx - v0;
            const float py = fy - v1;
            const int dx = c >> 1;          // corner order matches reference
            const int dy = c & 1;
            const float w = (dx ? (1.0f - px) : px) * (dy ? (1.0f - py) : py);
            int t1 = i - (sy + dy);
            t1 = min(max(t1, 0), CLIPM);
            int r = t1 - (sx + dx);
            r = min(max(r, 0), CLIPM);
            g_tap[e] = make_int2((kk * NR + r) * IMG_W, __float_as_int(w));
        }
        return;
    }

    const int k   = blockIdx.x / (NCH * JB);
    const int rem = blockIdx.x % (NCH * JB);
    const int r0  = (rem / JB) * 7;               // first output row of chunk
    const int j   = (rem % JB) * BS1 + tid;

    float p[PW * PW];
    #pragma unroll
    for (int t = 0; t < PW * PW; t++) p[t] = __ldg(&patterns[k * PW * PW + t]);
    float s = 0.0f;
    #pragma unroll
    for (int t = 0; t < PW * PW; t++) s += fabsf(p[t]);
    const float thr = 1.0f - s * (1.0f / 49.0f);

    float win[PW][PW];
    #pragma unroll
    for (int a = 0; a < PW; a++) {
        const int r = r0 - PW + a;
        #pragma unroll
        for (int b = 0; b < PW; b++) {
            const int c = j - PW + b;
            win[a][b] = (r >= 0 && c >= 0) ? __ldg(&x[r * IMG_W + c]) : 0.0f;
        }
    }

    #pragma unroll
    for (int step = 0; step < PW; step++) {
        const int row = r0 + step;
        float acc = 0.0f;
        #pragma unroll
        for (int a = 0; a < PW; a++)
            #pragma unroll
            for (int b = 0; b < PW; b++)
                acc += fabsf(p[a * PW + b] - win[a][b]);
        const float f = 1.0f - acc * (1.0f / 49.0f);
        g_F[(k * NR + row) * IMG_W + j] = (f > thr) ? f : 0.0f;

        if (step < PW - 1) {
            #pragma unroll
            for (int a = 0; a < PW - 1; a++)
                #pragma unroll
                for (int b = 0; b < PW; b++)
                    win[a][b] = win[a + 1][b];
            #pragma unroll
            for (int b = 0; b < PW; b++) {
                const int c = j - PW + b;
                win[PW - 1][b] = (c >= 0) ? __ldg(&x[row * IMG_W + c]) : 0.0f;
            }
        }
    }
}

// ---------------------------------------------------------------------------
// Kernel B: 2700 small blocks (225 classes x 12 col-tiles), 128 threads,
// thread = one column. 32 fully-unrolled independent LDG+FMA per thread;
// tap meta loads are block-uniform (L1 broadcast). Small blocks, no smem
// tile -> many resident blocks/SM -> latency hidden by occupancy, exactly
// the R2 configuration that measured fastest.
// ---------------------------------------------------------------------------
__global__ void __launch_bounds__(128) geneo3_kernel(float* __restrict__ out) {
    const int cls = blockIdx.x / JT3;
    const int j   = (blockIdx.x % JT3) * 128 + threadIdx.x;
    const int tid = threadIdx.x;

    float m = -3.0e38f;
    if (cls < __ldg(&g_icount)) {
        const int2* tp = &g_tap[cls * 32];
        float acc = 0.0f;
        #pragma unroll
        for (int t = 0; t < 32; t++) {
            const int2 mt = __ldg(&tp[t]);
            acc = fmaf(__int_as_float(mt.y), __ldg(&g_F[mt.x + j]), acc);
        }
        m = acc;
    }

    #pragma unroll
    for (int o = 16; o > 0; o >>= 1)
        m = fmaxf(m, __shfl_xor_sync(0xffffffffu, m, o));
    __shared__ float smax[4];
    if ((tid & 31) == 0) smax[tid >> 5] = m;
    __syncthreads();
    if (tid == 0) {
        m = fmaxf(fmaxf(smax[0], smax[1]), fmaxf(smax[2], smax[3]));
        atomicMax(&g_enc, enc_f(m));
        __threadfence();
        const unsigned old = atomicAdd(&g_done, 1u);
        if (old == (unsigned)(NBLK3 - 1)) {
            const unsigned u = atomicOr(&g_enc, 0u);   // coherent read
            out[0] = dec_f(u) * (1.0f / 7.0f);
        }
    }
}

extern "C" void kernel_launch(void* const* d_in, const int* in_sizes, int n_in,
                              void* d_out, int out_size) {
    const float* x        = (const float*)d_in[0];
    const float* patterns = (const float*)d_in[1];
    const float* vectors  = (const float*)d_in[2];
    float* out = (float*)d_out;

    geneo1_kernel<<<NBLK1 + 1, BS1>>>(x, patterns, vectors);
    geneo3_kernel<<<NBLK3, 128>>>(out);
}